// round 1
// baseline (speedup 1.0000x reference)
#include <cuda_runtime.h>
#include <math.h>
#include <stdint.h>

#define L_    1024
#define NB    4
#define E_    512
#define H_    8
#define D_    32
#define DFF_  2048
#define E2_   256
#define TOK   4096      // L*NB
#define PM    2047      // 2L-1
#define KW    31

// ---------------- scratch (static device globals; no allocation) -------------
__device__ float g_h1[(size_t)TOK * DFF_];      // FFN hidden (reused)
__device__ float g_x[(size_t)TOK * E_];         // x after macaron
__device__ float g_qkv[(size_t)TOK * 768];
__device__ float g_p[(size_t)PM * 256 + 256];
__device__ float g_total[(size_t)32 * 1024 * 1024];   // (N,H,L,S) scores/attn
__device__ float g_ctx[(size_t)TOK * E2_];
__device__ float g_x2[(size_t)TOK * E_];
__device__ float g_y[(size_t)TOK * 1024];
__device__ float g_hglu[(size_t)NB * E_ * L_];  // (n,c,l)
__device__ float g_hct[(size_t)TOK * E_];
__device__ float g_x3[(size_t)TOK * E_];
__device__ float g_x4[(size_t)TOK * E_];

// ---------------- generic SGEMM: C = A(MxK) * B(NxK)^T + bias (+epi) ---------
// EPI: 0 = bias; 1 = bias + DoubleSwish; 2 = bias + residual add
template <int EPI>
__global__ __launch_bounds__(256) void sgemm(
    const float* __restrict__ A, const float* __restrict__ B,
    const float* __restrict__ bias, const float* __restrict__ res,
    float* __restrict__ C, int M, int Nn, int Kk)
{
    __shared__ float As[16][128];
    __shared__ float Bs[16][128];
    const int tid  = threadIdx.x;
    const int row0 = blockIdx.y * 128;
    const int col0 = blockIdx.x * 128;
    const int trow = (tid / 16) * 8;
    const int tcol = (tid % 16) * 8;

    float acc[8][8];
#pragma unroll
    for (int i = 0; i < 8; i++)
#pragma unroll
        for (int j = 0; j < 8; j++) acc[i][j] = 0.f;

    const int lr = tid / 4;          // 0..63
    const int lc = (tid % 4) * 4;    // 0,4,8,12

    for (int k0 = 0; k0 < Kk; k0 += 16) {
#pragma unroll
        for (int r = 0; r < 2; r++) {
            int arow = row0 + lr + r * 64;
            float4 v = make_float4(0.f, 0.f, 0.f, 0.f);
            if (arow < M) v = *(const float4*)(A + (size_t)arow * Kk + k0 + lc);
            As[lc + 0][lr + r * 64] = v.x;
            As[lc + 1][lr + r * 64] = v.y;
            As[lc + 2][lr + r * 64] = v.z;
            As[lc + 3][lr + r * 64] = v.w;
            int brow = col0 + lr + r * 64;
            float4 w = make_float4(0.f, 0.f, 0.f, 0.f);
            if (brow < Nn) w = *(const float4*)(B + (size_t)brow * Kk + k0 + lc);
            Bs[lc + 0][lr + r * 64] = w.x;
            Bs[lc + 1][lr + r * 64] = w.y;
            Bs[lc + 2][lr + r * 64] = w.z;
            Bs[lc + 3][lr + r * 64] = w.w;
        }
        __syncthreads();
#pragma unroll
        for (int kk = 0; kk < 16; kk++) {
            float ra[8], rb[8];
#pragma unroll
            for (int i = 0; i < 8; i++) ra[i] = As[kk][trow + i];
#pragma unroll
            for (int j = 0; j < 8; j++) rb[j] = Bs[kk][tcol + j];
#pragma unroll
            for (int i = 0; i < 8; i++)
#pragma unroll
                for (int j = 0; j < 8; j++)
                    acc[i][j] = fmaf(ra[i], rb[j], acc[i][j]);
        }
        __syncthreads();
    }

#pragma unroll
    for (int i = 0; i < 8; i++) {
        int row = row0 + trow + i;
        if (row >= M) continue;
#pragma unroll
        for (int j = 0; j < 8; j++) {
            int col = col0 + tcol + j;
            if (col >= Nn) continue;
            float v = acc[i][j];
            if (bias) v += bias[col];
            if (EPI == 1) v = v / (1.f + expf(1.f - v));     // x*sigmoid(x-1)
            if (EPI == 2) v += res[(size_t)row * Nn + col];
            C[(size_t)row * Nn + col] = v;
        }
    }
}

// -------- expand attn_scores_in through proj_in into total[n,h,l,s] ----------
__global__ __launch_bounds__(256) void proj_in_kernel(
    const float* __restrict__ asi, const float* __restrict__ proj,
    float* __restrict__ total)
{
    __shared__ float pm[64];
    if (threadIdx.x < 64) pm[threadIdx.x] = proj[threadIdx.x];
    __syncthreads();
    size_t idx = (size_t)blockIdx.x * 256 + threadIdx.x;  // (n,l,s) over 4M
    int n = (int)(idx >> 20);
    size_t ls = idx & ((1u << 20) - 1);
    const float4* s = (const float4*)(asi + idx * 8);
    float4 a0 = s[0], a1 = s[1];
    float a[8] = {a0.x, a0.y, a0.z, a0.w, a1.x, a1.y, a1.z, a1.w};
#pragma unroll
    for (int g = 0; g < 8; g++) {
        float sum = 0.f;
#pragma unroll
        for (int hh = 0; hh < 8; hh++) sum = fmaf(a[hh], pm[hh * 8 + g], sum);
        total[(((size_t)(n * 8 + g)) << 20) + ls] = sum;
    }
}

// -------- total += (ac + rel_shift(bd)) * scaling -----------------------------
__global__ __launch_bounds__(256) void scores_kernel(
    const float* __restrict__ qkv, const float* __restrict__ p,
    const float* __restrict__ pu, const float* __restrict__ pv,
    float* __restrict__ total)
{
    __shared__ float qu[64][33], qv[64][33], ks[64][33], ps[128][33];
    const int tid = threadIdx.x;
    const int nh = blockIdx.z;
    const int n = nh >> 3, h = nh & 7;
    const int l0 = blockIdx.y * 64;
    const int s0 = blockIdx.x * 64;
    const int mbase = (L_ - 64) - l0 + s0;

#pragma unroll
    for (int t = 0; t < 8; t++) {
        int flat = tid + 256 * t;              // 0..2047
        int r = flat >> 5, dd = flat & 31;
        float u = pu[h * 32 + dd], vb = pv[h * 32 + dd];
        float qval = qkv[(size_t)((l0 + r) * NB + n) * 768 + h * 32 + dd];
        qu[r][dd] = qval + u;
        qv[r][dd] = qval + vb;
        ks[r][dd] = qkv[(size_t)((s0 + r) * NB + n) * 768 + 256 + h * 32 + dd];
    }
#pragma unroll
    for (int t = 0; t < 16; t++) {
        int flat = tid + 256 * t;              // 0..4095
        int r = flat >> 5, dd = flat & 31;
        int m = mbase + r;
        ps[r][dd] = (m < PM) ? p[(size_t)m * 256 + h * 32 + dd] : 0.f;
    }
    __syncthreads();

    const int trow = (tid >> 4) * 4;
    const int tcol = (tid & 15) * 4;
    const int pbase = 63 - trow + tcol;        // diag base (i=0,j=0)
    float ac[4][4] = {}, bd[4][4] = {};
#pragma unroll
    for (int dd = 0; dd < 32; dd++) {
        float ru[4], rv[4], rk[4], rp[7];
#pragma unroll
        for (int i = 0; i < 4; i++) { ru[i] = qu[trow + i][dd]; rv[i] = qv[trow + i][dd]; }
#pragma unroll
        for (int j = 0; j < 4; j++) rk[j] = ks[tcol + j][dd];
#pragma unroll
        for (int t = 0; t < 7; t++) rp[t] = ps[pbase + t - 3][dd];
#pragma unroll
        for (int i = 0; i < 4; i++)
#pragma unroll
            for (int j = 0; j < 4; j++) {
                ac[i][j] = fmaf(ru[i], rk[j], ac[i][j]);
                bd[i][j] = fmaf(rv[i], rp[j - i + 3], bd[i][j]);
            }
    }
    const float scal = 0.17677669529663687f;   // 1/sqrt(32)
    size_t base = (((size_t)nh) << 20) + (size_t)(l0 + trow) * L_ + s0 + tcol;
#pragma unroll
    for (int i = 0; i < 4; i++) {
        size_t rowb = base + (size_t)i * L_;
#pragma unroll
        for (int j = 0; j < 4; j++)
            total[rowb + j] += (ac[i][j] + bd[i][j]) * scal;
    }
}

// -------- scores_out[n,l,s,g] = sum_h total*proj_out + asi --------------------
__global__ __launch_bounds__(256) void scores_out_kernel(
    const float* __restrict__ total, const float* __restrict__ asi,
    const float* __restrict__ proj, float* __restrict__ out)
{
    __shared__ float pm[64];
    if (threadIdx.x < 64) pm[threadIdx.x] = proj[threadIdx.x];
    __syncthreads();
    size_t idx = (size_t)blockIdx.x * 256 + threadIdx.x;
    int n = (int)(idx >> 20);
    size_t ls = idx & ((1u << 20) - 1);
    float tt[8];
#pragma unroll
    for (int hh = 0; hh < 8; hh++)
        tt[hh] = total[(((size_t)(n * 8 + hh)) << 20) + ls];
    const float4* s = (const float4*)(asi + idx * 8);
    float4 a0 = s[0], a1 = s[1];
    float a[8] = {a0.x, a0.y, a0.z, a0.w, a1.x, a1.y, a1.z, a1.w};
    float o[8];
#pragma unroll
    for (int g = 0; g < 8; g++) {
        float sum = a[g];
#pragma unroll
        for (int hh = 0; hh < 8; hh++) sum = fmaf(tt[hh], pm[hh * 8 + g], sum);
        o[g] = sum;
    }
    float4* dst = (float4*)(out + idx * 8);
    dst[0] = make_float4(o[0], o[1], o[2], o[3]);
    dst[1] = make_float4(o[4], o[5], o[6], o[7]);
}

// -------- in-place softmax over last dim (row = 1024) --------------------------
__global__ __launch_bounds__(256) void softmax_kernel(float* __restrict__ total)
{
    __shared__ float red[8];
    float* ptr = total + (((size_t)blockIdx.x) << 10);
    float4 v = ((float4*)ptr)[threadIdx.x];
    float m = fmaxf(fmaxf(v.x, v.y), fmaxf(v.z, v.w));
#pragma unroll
    for (int o = 16; o > 0; o >>= 1) m = fmaxf(m, __shfl_xor_sync(0xffffffffu, m, o));
    if ((threadIdx.x & 31) == 0) red[threadIdx.x >> 5] = m;
    __syncthreads();
    m = red[0];
#pragma unroll
    for (int i = 1; i < 8; i++) m = fmaxf(m, red[i]);
    float e0 = expf(v.x - m), e1 = expf(v.y - m), e2 = expf(v.z - m), e3 = expf(v.w - m);
    float s = e0 + e1 + e2 + e3;
#pragma unroll
    for (int o = 16; o > 0; o >>= 1) s += __shfl_xor_sync(0xffffffffu, s, o);
    __syncthreads();
    if ((threadIdx.x & 31) == 0) red[threadIdx.x >> 5] = s;
    __syncthreads();
    s = red[0] + red[1] + red[2] + red[3] + red[4] + red[5] + red[6] + red[7];
    float inv = 1.f / s;
    ((float4*)ptr)[threadIdx.x] = make_float4(e0 * inv, e1 * inv, e2 * inv, e3 * inv);
}

// -------- ctx[l,n,h*32+d] = sum_s attn[n,h,l,s] * v[s,n,h,d] -------------------
__global__ __launch_bounds__(256) void av_kernel(
    const float* __restrict__ attn, const float* __restrict__ qkv,
    float* __restrict__ ctx)
{
    const int nh = blockIdx.y;
    const int n = nh >> 3, h = nh & 7;
    const int l0 = blockIdx.x * 64;
    __shared__ float As[64][65];
    __shared__ float Vs[64][33];
    const int tid = threadIdx.x;
    const int col = tid & 31;
    const int rg  = tid >> 5;
    float acc[8] = {};
    const float* Abase = attn + (((size_t)nh) << 20) + (((size_t)l0) << 10);
    for (int s0 = 0; s0 < 1024; s0 += 64) {
#pragma unroll
        for (int t = 0; t < 4; t++) {
            int f4 = tid + 256 * t;
            int r = f4 >> 4;
            int c4 = (f4 & 15) * 4;
            float4 v = *(const float4*)(Abase + (((size_t)r) << 10) + s0 + c4);
            As[r][c4] = v.x; As[r][c4 + 1] = v.y; As[r][c4 + 2] = v.z; As[r][c4 + 3] = v.w;
        }
#pragma unroll
        for (int t = 0; t < 8; t++) {
            int flat = tid + 256 * t;
            int r = flat >> 5, dd = flat & 31;
            Vs[r][dd] = qkv[(size_t)((s0 + r) * NB + n) * 768 + 512 + h * 32 + dd];
        }
        __syncthreads();
#pragma unroll
        for (int kk = 0; kk < 64; kk++) {
            float vv = Vs[kk][col];
#pragma unroll
            for (int i = 0; i < 8; i++)
                acc[i] = fmaf(As[rg * 8 + i][kk], vv, acc[i]);
        }
        __syncthreads();
    }
#pragma unroll
    for (int i = 0; i < 8; i++) {
        int l = l0 + rg * 8 + i;
        ctx[(size_t)(l * NB + n) * 256 + h * 32 + col] = acc[i];
    }
}

// -------- GLU + transpose to (n,c,l) ------------------------------------------
__global__ __launch_bounds__(256) void glu_kernel(
    const float* __restrict__ y, float* __restrict__ hglu)
{
    size_t idx = (size_t)blockIdx.x * 256 + threadIdx.x;  // (n,c,l) over 2M
    int l = (int)(idx & 1023);
    int c = (int)((idx >> 10) & 511);
    int n = (int)(idx >> 19);
    size_t t = (size_t)l * NB + n;
    float a = y[t * 1024 + c];
    float b = y[t * 1024 + c + 512];
    hglu[idx] = a / (1.f + expf(-b));
}

// -------- depthwise conv(K=31) + bias + DoubleSwish, write token-major --------
__global__ __launch_bounds__(256) void dwconv_kernel(
    const float* __restrict__ hglu, const float* __restrict__ w,
    const float* __restrict__ b, float* __restrict__ out)
{
    const int nc = blockIdx.x;          // n*512 + c
    const int c = nc & 511, n = nc >> 9;
    __shared__ float sm[L_ + 30];
    __shared__ float wc[KW];
    const float* row = hglu + (((size_t)nc) << 10);
    for (int i = threadIdx.x; i < L_ + 30; i += 256) {
        int l = i - 15;
        sm[i] = (l >= 0 && l < L_) ? row[l] : 0.f;
    }
    if (threadIdx.x < KW) wc[threadIdx.x] = w[c * KW + threadIdx.x];
    __syncthreads();
    const float bb = b[c];
    for (int l = threadIdx.x; l < L_; l += 256) {
        float s = bb;
#pragma unroll
        for (int k = 0; k < KW; k++) s = fmaf(sm[l + k], wc[k], s);
        float v = s / (1.f + expf(1.f - s));
        out[(size_t)(l * NB + n) * E_ + c] = v;
    }
}

// -------- BasicNorm -> d_out ---------------------------------------------------
__global__ __launch_bounds__(128) void norm_kernel(
    const float* __restrict__ x, const float* __restrict__ leps,
    float* __restrict__ out)
{
    __shared__ float red[4];
    const size_t base = (size_t)blockIdx.x * 512;
    float4 v = ((const float4*)(x + base))[threadIdx.x];
    float ss = v.x * v.x + v.y * v.y + v.z * v.z + v.w * v.w;
#pragma unroll
    for (int o = 16; o > 0; o >>= 1) ss += __shfl_xor_sync(0xffffffffu, ss, o);
    if ((threadIdx.x & 31) == 0) red[threadIdx.x >> 5] = ss;
    __syncthreads();
    float tot = red[0] + red[1] + red[2] + red[3];
    float scale = rsqrtf(tot * (1.f / 512.f) + expf(leps[0]));
    ((float4*)(out + base))[threadIdx.x] =
        make_float4(v.x * scale, v.y * scale, v.z * scale, v.w * scale);
}

// ------------------------------- launcher -------------------------------------
extern "C" void kernel_launch(void* const* d_in, const int* in_sizes, int n_in,
                              void* d_out, int out_size)
{
    const float* src      = (const float*)d_in[0];
    const float* pos_emb  = (const float*)d_in[1];
    const float* asi      = (const float*)d_in[2];
    const float* w_in     = (const float*)d_in[3];
    const float* b_in     = (const float*)d_in[4];
    const float* w_pos    = (const float*)d_in[5];
    const float* pbu      = (const float*)d_in[6];
    const float* pbv      = (const float*)d_in[7];
    const float* projIn   = (const float*)d_in[8];
    const float* projOut  = (const float*)d_in[9];
    const float* w_out    = (const float*)d_in[10];
    const float* b_out    = (const float*)d_in[11];
    const float* w_ff1m   = (const float*)d_in[12];
    const float* b_ff1m   = (const float*)d_in[13];
    const float* w_ff2m   = (const float*)d_in[14];
    const float* b_ff2m   = (const float*)d_in[15];
    const float* w_ff1    = (const float*)d_in[16];
    const float* b_ff1    = (const float*)d_in[17];
    const float* w_ff2    = (const float*)d_in[18];
    const float* b_ff2    = (const float*)d_in[19];
    const float* w_pw1    = (const float*)d_in[20];
    const float* b_pw1    = (const float*)d_in[21];
    const float* w_dw     = (const float*)d_in[22];
    const float* b_dw     = (const float*)d_in[23];
    const float* w_pw2    = (const float*)d_in[24];
    const float* b_pw2    = (const float*)d_in[25];
    const float* leps     = (const float*)d_in[26];

    float* out        = (float*)d_out;
    float* out_scores = out + (size_t)TOK * E_;   // x first, then scores_out

    float *h1, *x, *qkv, *p, *total, *ctx, *x2, *y, *hglu, *hct, *x3, *x4;
    cudaGetSymbolAddress((void**)&h1,   g_h1);
    cudaGetSymbolAddress((void**)&x,    g_x);
    cudaGetSymbolAddress((void**)&qkv,  g_qkv);
    cudaGetSymbolAddress((void**)&p,    g_p);
    cudaGetSymbolAddress((void**)&total,g_total);
    cudaGetSymbolAddress((void**)&ctx,  g_ctx);
    cudaGetSymbolAddress((void**)&x2,   g_x2);
    cudaGetSymbolAddress((void**)&y,    g_y);
    cudaGetSymbolAddress((void**)&hglu, g_hglu);
    cudaGetSymbolAddress((void**)&hct,  g_hct);
    cudaGetSymbolAddress((void**)&x3,   g_x3);
    cudaGetSymbolAddress((void**)&x4,   g_x4);

    // macaron FFN
    sgemm<1><<<dim3(DFF_ / 128, TOK / 128), 256>>>(src, w_ff1m, b_ff1m, nullptr, h1, TOK, DFF_, E_);
    sgemm<2><<<dim3(E_ / 128, TOK / 128), 256>>>(h1, w_ff2m, b_ff2m, src, x, TOK, E_, DFF_);

    // attention inputs
    sgemm<0><<<dim3(768 / 128, TOK / 128), 256>>>(x, w_in, b_in, nullptr, qkv, TOK, 768, E_);
    sgemm<0><<<dim3(2, 16), 256>>>(pos_emb, w_pos, nullptr, nullptr, p, PM, 256, E_);

    // scores
    proj_in_kernel<<<16384, 256>>>(asi, projIn, total);
    scores_kernel<<<dim3(16, 16, 32), 256>>>(qkv, p, pbu, pbv, total);
    scores_out_kernel<<<16384, 256>>>(total, asi, projOut, out_scores);
    softmax_kernel<<<32768, 256>>>(total);
    av_kernel<<<dim3(16, 32), 256>>>(total, qkv, ctx);
    sgemm<2><<<dim3(E_ / 128, TOK / 128), 256>>>(ctx, w_out, b_out, x, x2, TOK, E_, E2_);

    // conv module
    sgemm<0><<<dim3(1024 / 128, TOK / 128), 256>>>(x2, w_pw1, b_pw1, nullptr, y, TOK, 1024, E_);
    glu_kernel<<<8192, 256>>>(y, hglu);
    dwconv_kernel<<<2048, 256>>>(hglu, w_dw, b_dw, hct);
    sgemm<2><<<dim3(E_ / 128, TOK / 128), 256>>>(hct, w_pw2, b_pw2, x2, x3, TOK, E_, E_);

    // final FFN + BasicNorm
    sgemm<1><<<dim3(DFF_ / 128, TOK / 128), 256>>>(x3, w_ff1, b_ff1, nullptr, h1, TOK, DFF_, E_);
    sgemm<2><<<dim3(E_ / 128, TOK / 128), 256>>>(h1, w_ff2, b_ff2, x3, x4, TOK, E_, DFF_);
    norm_kernel<<<TOK, 128>>>(x4, leps, out);
}